// round 16
// baseline (speedup 1.0000x reference)
#include <cuda_runtime.h>
#include <math.h>

// ---------------- constants (from reference) ----------------
#define SPIN_LEN   100
#define TRAIN_LEN  200000
#define ML_C       2.9086f
#define SL_C       1.898f
#define L2E        1.4426950408889634f

#define CHT     4                    // output steps per thread
#define TB      128                  // threads per scan block (4 warps)
#define WARM    24                   // discarded convergence steps (multiple of 4)
#define OUTB    (TB * CHT)           // 512 output steps per block
#define NWB     (WARM + OUTB)        // 536-step shared input window per block
#define SK4(g)  ((g) + ((g) >> 3))   // float4 skew: conflict-free at stride 4
#define SWIN4   (SK4(NWB - 1) + 1)   // 602
#define SKO(t)  ((t) + ((t) >> 5))   // float skew for output transpose buffer
#define SOUT    (SKO(OUTB - 1) + 1)  // 527

#define STD_N   (TRAIN_LEN - SPIN_LEN)   // 199900 floats = 49975 float4 exactly
#define STD_N4  (STD_N / 4)              // 49975
#define SB      196                      // 196*256 = 50176 threads >= 49975

// ---------------- device scratch ----------------
__device__ float  g_ps[SB];
__device__ float  g_pq[SB];
__device__ float4 g_P0;              // thr, oo1, ol1, a1n
__device__ float4 g_P1;              // k01n, a2n, k02n, (unused)

__device__ __forceinline__ float ex2f(float x) { float y; asm("ex2.approx.f32 %0, %1;" : "=f"(y) : "f"(x)); return y; }
__device__ __forceinline__ float rcpf(float x) { float y; asm("rcp.approx.f32 %0, %1;" : "=f"(y) : "f"(x)); return y; }

// ---------------- std pass 1: single-wave float4 partial sums ----------------
// Block 0 / lane 0 of warp 1 additionally derives the scalar params AFTER the
// barrier — concurrent with tid 0's final reduce, so it only delays block 0
// (~700 cyc), never a consumer warp inside k_scan.
__global__ void __launch_bounds__(256)
k_std1(const float* __restrict__ y,
       const float* cmean, const float* cstd,
       const float* W_rom, const float* W_rlm, const float* W_rfm,
       const float* b0_yom, const float* W_b1_yom,
       const float* b0_ylm, const float* W_b2_ylm,
       const float* theltaC)
{
    __shared__ float ss[8], sq[8];
    const int tid = threadIdx.x;
    const int gi  = blockIdx.x * 256 + tid;

    float a = 0.0f, b = 0.0f;
    if (gi < STD_N4) {
        // y + SPIN_LEN is 16B-aligned (100 floats = 400 bytes)
        float4 v = reinterpret_cast<const float4*>(y + SPIN_LEN)[gi];
        a = ((v.x + v.y) + (v.z + v.w));
        b = fmaf(v.x, v.x, fmaf(v.y, v.y, fmaf(v.z, v.z, v.w * v.w)));
    }
    #pragma unroll
    for (int o = 16; o > 0; o >>= 1) {
        a += __shfl_down_sync(0xffffffffu, a, o);
        b += __shfl_down_sync(0xffffffffu, b, o);
    }
    if ((tid & 31) == 0) { ss[tid >> 5] = a; sq[tid >> 5] = b; }
    __syncthreads();
    if (tid == 0) {
        float sa = 0.0f, sb = 0.0f;
        #pragma unroll
        for (int w = 0; w < 8; ++w) { sa += ss[w]; sb += sq[w]; }
        g_ps[blockIdx.x] = sa;
        g_pq[blockIdx.x] = sb;
    }
    if (blockIdx.x == 0 && tid == 32) {
        float eo  = expf(W_rom[0]);
        float el  = expf(W_rlm[0]);
        float den = eo + el + expf(W_rfm[0]);
        float a1  = W_b1_yom[0] / cstd[0];
        float a2  = W_b2_ylm[0] / SL_C;
        g_P0 = make_float4(expf(theltaC[0]),                    // thr
                           eo / den,                            // oo1
                           el / den,                            // ol1
                           -a1 * L2E);                          // a1n
        g_P1 = make_float4(-(b0_yom[0] - cmean[0] * a1) * L2E,  // k01n
                           -a2 * L2E,                           // a2n
                           -(b0_ylm[0] - ML_C * a2) * L2E,      // k02n
                           0.0f);
    }
}

// ---------------- main chunked-warmup scan (R13 body, measured 8.86us) ------
// 512 blocks x 128 threads. Block shares one 536-step window; thread t: 24
// discarded + 4 emitted steps. Params arrive precomputed (2 broadcast float4
// loads); the 196 std partials are block-reduced here (2 LDG/thread, fixed
// order -> deterministic, identical across blocks).
__global__ void __launch_bounds__(TB)
k_scan(const float* __restrict__ x, float* __restrict__ out, int B)
{
    __shared__ float4 sw[SWIN4];
    __shared__ float  ob[10 * SOUT];
    __shared__ float  rs[8];         // 4 warp partial (sa,sb) pairs
    __shared__ float  sstd;

    const int tid    = threadIdx.x;
    const int base   = blockIdx.x * OUTB;   // first emitted global step
    const int wstart = base - WARM;         // window start (may be < 0)

    // ---- issue all global loads up front (latencies overlap) ----
    float2 xv[5];
    #pragma unroll
    for (int m = 0; m < 5; ++m) {
        int g = tid + TB * m;
        int i = wstart + g;
        xv[m] = make_float2(0.0f, 0.0f);
        if (g < NWB && i >= 0)
            xv[m] = reinterpret_cast<const float2*>(x)[i];
    }
    float pa = 0.0f, pb = 0.0f;
    if (tid < SB)      { pa += g_ps[tid];      pb += g_pq[tid]; }
    if (tid + TB < SB) { pa += g_ps[tid + TB]; pb += g_pq[tid + TB]; }
    const float4 P0 = g_P0, P1 = g_P1;       // broadcast loads (L2-hot)
    const float thr = P0.x, oo1 = P0.y, ol1 = P0.z, a1n = P0.w;
    const float k01n = P1.x, a2n = P1.y, k02n = P1.z;

    // ---- stage window + precompute ol(u2) ----
    // Zero-fill for steps < 0 keeps c == 0 exactly (m=min(0,thr)=0, olcc=0).
    #pragma unroll
    for (int m = 0; m < 5; ++m) {
        int g = tid + TB * m;
        if (g < NWB) {
            float ol = ol1 * rcpf(1.0f + ex2f(fmaf(xv[m].y, a2n, k02n)));
            if (wstart + g < 0) ol = 0.0f;
            sw[SK4(g)] = make_float4(xv[m].x, xv[m].y, ol, 0.0f);
        }
    }

    // ---- std final reduce (block-wide, fixed order -> deterministic) ----
    #pragma unroll
    for (int o = 16; o > 0; o >>= 1) {
        pa += __shfl_down_sync(0xffffffffu, pa, o);
        pb += __shfl_down_sync(0xffffffffu, pb, o);
    }
    if ((tid & 31) == 0) { rs[(tid >> 5) * 2] = pa; rs[(tid >> 5) * 2 + 1] = pb; }
    __syncthreads();                          // also covers window staging
    if (tid == 0) {
        float sa = (rs[0] + rs[2]) + (rs[4] + rs[6]);
        float sb = (rs[1] + rs[3]) + (rs[5] + rs[7]);
        const float n = (float)STD_N;
        float mean = sa / n;
        sstd = sqrtf((sb - sa * mean) / (n - 1.0f));
    }
    __syncthreads();
    const float stdv = sstd;

    const int g0 = tid * CHT;          // chain window start (multiple of 4)
    float c = 0.0f;

    // ---- warmup: divide-free, affine smem addressing ----
    // 4-aligned 4-step ranges never cross an 8-boundary -> (g)>>3 constant
    // per range -> base pointer + immediate offsets.
    // step: m = min(u1, thr-c); olcc = min(ol*c, u2); c' = fma(-oo1*c, s, (c-olcc)+m)
    #pragma unroll
    for (int k0 = 0; k0 < WARM; k0 += 4) {
        const float4* p = &sw[SK4(g0 + k0)];
        #pragma unroll
        for (int k = 0; k < 4; ++k) {
            float4 v = p[k];
            float s    = rcpf(1.0f + ex2f(fmaf(c, a1n, k01n)));
            float t    = oo1 * c;
            float olcc = fminf(v.z * c, v.y);
            float m    = fminf(v.x, thr - c);
            c = fmaf(-t, s, (c - olcc) + m);
        }
    }

    // ---- output phase: 4 steps into smem transpose buffer ----
    const int sb0 = CHT * tid + (tid >> 3);   // SKO(4*tid), k-invariant base
    {
        const float4* p = &sw[SK4(g0 + WARM)];
        #pragma unroll
        for (int k = 0; k < CHT; ++k) {
            float4 v = p[k];
            float* q = &ob[sb0 + k];

            float s    = rcpf(1.0f + ex2f(fmaf(c, a1n, k01n)));
            float oo   = oo1 * s;
            float ooc  = oo * c;
            float olc  = (c > 0.0f) ? fminf(v.z, v.y * rcpf(c)) : v.z;
            float olcc = olc * c;
            float px   = fmaxf(v.x + c - thr, 0.0f);
            float ib   = (v.x > 0.0f) ? px * rcpf(v.x) : 0.0f;
            float f    = (1.0f - oo) - olc;

            q[0 * SOUT] = ooc + px;   // h_n
            q[1 * SOUT] = c;          // c_n (pre-update)
            q[2 * SOUT] = v.z * c;    // l_n
            q[3 * SOUT] = olcc;       // lc_n
            q[4 * SOUT] = px;         // bp_n
            q[5 * SOUT] = ib;         // g_ib
            q[6 * SOUT] = oo;         // g_oo
            q[7 * SOUT] = v.z;        // g_ol
            q[8 * SOUT] = olc;        // g_olc
            q[9 * SOUT] = f;          // g_f

            c = ((c - ooc) - olcc) + (v.x - px);
        }
    }
    __syncthreads();

    // ---- coalesced flush (also produces h_nout and obs_std streams) ----
    #pragma unroll
    for (int st = 0; st < 10; ++st) {
        #pragma unroll
        for (int m = 0; m < OUTB / TB; ++m) {
            int t = tid + TB * m;
            out[(size_t)st * B + base + t] = ob[st * SOUT + t + (t >> 5)];
        }
    }
    float2* o2 = reinterpret_cast<float2*>(out + 10 * (size_t)B);
    #pragma unroll
    for (int m = 0; m < OUTB / TB; ++m) {
        int t = tid + TB * m;
        o2[base + t] = make_float2(ob[t + (t >> 5)], stdv);   // h_nout = [h, std]
        out[12 * (size_t)B + base + t] = stdv;                // obs_std
    }
}

// ---------------- launch ----------------
extern "C" void kernel_launch(void* const* d_in, const int* in_sizes, int n_in,
                              void* d_out, int out_size)
{
    const float* x = (const float*)d_in[0];
    const float* y = (const float*)d_in[1];
    float* out = (float*)d_out;
    const int B = in_sizes[0] / 2;   // 262144

    k_std1<<<SB, 256>>>(y,
                        (const float*)d_in[2], (const float*)d_in[3],
                        (const float*)d_in[4], (const float*)d_in[5],
                        (const float*)d_in[6], (const float*)d_in[7],
                        (const float*)d_in[8], (const float*)d_in[9],
                        (const float*)d_in[10], (const float*)d_in[11]);

    const int blocks = B / OUTB;     // 512 blocks x 128 threads
    k_scan<<<blocks, TB>>>(x, out, B);
}

// round 17
// speedup vs baseline: 1.0313x; 1.0313x over previous
#include <cuda_runtime.h>
#include <math.h>

// ---------------- constants (from reference) ----------------
#define SPIN_LEN   100
#define TRAIN_LEN  200000
#define ML_C       2.9086f
#define SL_C       1.898f
#define L2E        1.4426950408889634f

#define CHT     4                    // output steps per thread
#define TB      128                  // threads per scan block (4 warps)
#define WARM    24                   // discarded convergence steps (multiple of 4)
#define OUTB    (TB * CHT)           // 512 output steps per block
#define NWB     (WARM + OUTB)        // 536-step shared input window per block
#define SK4(g)  ((g) + ((g) >> 3))   // float4 skew: conflict-free at stride 4
#define SWIN4   (SK4(NWB - 1) + 1)   // 602
#define SKO(t)  ((t) + ((t) >> 5))   // float skew for output transpose buffer
#define SOUT    (SKO(OUTB - 1) + 1)  // 527

#define STD_N   (TRAIN_LEN - SPIN_LEN)   // 199900 floats = 49975 float4 exactly
#define STD_N4  (STD_N / 4)              // 49975
#define SB      196                      // 196*256 = 50176 threads >= 49975

// ---------------- device scratch ----------------
__device__ float  g_ps[SB];
__device__ float  g_pq[SB];
__device__ float4 g_P0;              // thr, oo1, ol1, a1n
__device__ float4 g_P1;              // k01n, a2n, k02n, (unused)

__device__ __forceinline__ float ex2f(float x) { float y; asm("ex2.approx.f32 %0, %1;" : "=f"(y) : "f"(x)); return y; }
__device__ __forceinline__ float rcpf(float x) { float y; asm("rcp.approx.f32 %0, %1;" : "=f"(y) : "f"(x)); return y; }

// ---------------- std pass 1: single-wave float4 partial sums ----------------
// Param derivation rides in block 0 / tid 32 with its 10 scalar loads ISSUED
// AT KERNEL ENTRY, so their cold-DRAM latency overlaps the block's own y-load
// latency instead of serializing after the reduce (the R16 mistake).
__global__ void __launch_bounds__(256)
k_std1(const float* __restrict__ y,
       const float* cmean, const float* cstd,
       const float* W_rom, const float* W_rlm, const float* W_rfm,
       const float* b0_yom, const float* W_b1_yom,
       const float* b0_ylm, const float* W_b2_ylm,
       const float* theltaC)
{
    __shared__ float ss[8], sq[8];
    const int tid = threadIdx.x;
    const int gi  = blockIdx.x * 256 + tid;
    const bool do_params = (blockIdx.x == 0) && (tid == 32);

    // ---- issue param loads FIRST (10 independent LDGs, predicated) ----
    float l_rom = 0.f, l_rlm = 0.f, l_rfm = 0.f, l_thc = 0.f, l_b1 = 0.f;
    float l_cs = 1.f, l_b2 = 0.f, l_b0o = 0.f, l_cm = 0.f, l_b0l = 0.f;
    if (do_params) {
        l_rom = W_rom[0];   l_rlm = W_rlm[0]; l_rfm = W_rfm[0];
        l_thc = theltaC[0]; l_b1  = W_b1_yom[0]; l_cs = cstd[0];
        l_b2  = W_b2_ylm[0]; l_b0o = b0_yom[0]; l_cm = cmean[0];
        l_b0l = b0_ylm[0];
    }

    // ---- y partial sums (overlaps the param loads above) ----
    float a = 0.0f, b = 0.0f;
    if (gi < STD_N4) {
        // y + SPIN_LEN is 16B-aligned (100 floats = 400 bytes)
        float4 v = reinterpret_cast<const float4*>(y + SPIN_LEN)[gi];
        a = ((v.x + v.y) + (v.z + v.w));
        b = fmaf(v.x, v.x, fmaf(v.y, v.y, fmaf(v.z, v.z, v.w * v.w)));
    }
    #pragma unroll
    for (int o = 16; o > 0; o >>= 1) {
        a += __shfl_down_sync(0xffffffffu, a, o);
        b += __shfl_down_sync(0xffffffffu, b, o);
    }
    if ((tid & 31) == 0) { ss[tid >> 5] = a; sq[tid >> 5] = b; }

    // ---- params: compute while the block reduce proceeds ----
    if (do_params) {
        float eo  = ex2f(l_rom * L2E);
        float el  = ex2f(l_rlm * L2E);
        float den = eo + el + ex2f(l_rfm * L2E);
        float a1  = l_b1 / l_cs;
        float a2  = l_b2 / SL_C;
        g_P0 = make_float4(ex2f(l_thc * L2E),            // thr
                           eo / den,                     // oo1
                           el / den,                     // ol1
                           -a1 * L2E);                   // a1n
        g_P1 = make_float4(-(l_b0o - l_cm * a1) * L2E,   // k01n
                           -a2 * L2E,                    // a2n
                           -(l_b0l - ML_C * a2) * L2E,   // k02n
                           0.0f);
    }

    __syncthreads();
    if (tid == 0) {
        float sa = 0.0f, sb = 0.0f;
        #pragma unroll
        for (int w = 0; w < 8; ++w) { sa += ss[w]; sb += sq[w]; }
        g_ps[blockIdx.x] = sa;
        g_pq[blockIdx.x] = sb;
    }
}

// ---------------- main chunked-warmup scan ----------------
// 512 blocks x 128 threads (R13 body, measured best). Block shares one
// 536-step window; thread t: 24 discarded + 4 emitted steps. Two barriers
// only: sstd is finalized by tid 0 AFTER barrier #1, hidden under everyone
// else's warmup, and consumed only after the post-output barrier.
__global__ void __launch_bounds__(TB)
k_scan(const float* __restrict__ x, float* __restrict__ out, int B)
{
    __shared__ float4 sw[SWIN4];
    __shared__ float  ob[10 * SOUT];
    __shared__ float  rs[8];         // 4 warp partial (sa,sb) pairs
    __shared__ float  sstd;

    const int tid    = threadIdx.x;
    const int base   = blockIdx.x * OUTB;   // first emitted global step
    const int wstart = base - WARM;         // window start (may be < 0)

    // ---- issue all global loads up front (latencies overlap) ----
    float2 xv[5];
    #pragma unroll
    for (int m = 0; m < 5; ++m) {
        int g = tid + TB * m;
        int i = wstart + g;
        xv[m] = make_float2(0.0f, 0.0f);
        if (g < NWB && i >= 0)
            xv[m] = reinterpret_cast<const float2*>(x)[i];
    }
    float pa = 0.0f, pb = 0.0f;
    if (tid < SB)      { pa += g_ps[tid];      pb += g_pq[tid]; }
    if (tid + TB < SB) { pa += g_ps[tid + TB]; pb += g_pq[tid + TB]; }
    const float4 P0 = g_P0, P1 = g_P1;       // broadcast loads (L2-hot)
    const float thr = P0.x, oo1 = P0.y, ol1 = P0.z, a1n = P0.w;
    const float k01n = P1.x, a2n = P1.y, k02n = P1.z;

    // ---- stage window + precompute ol(u2) ----
    // Zero-fill for steps < 0 keeps c == 0 exactly (m=min(0,thr)=0, olcc=0).
    #pragma unroll
    for (int m = 0; m < 5; ++m) {
        int g = tid + TB * m;
        if (g < NWB) {
            float ol = ol1 * rcpf(1.0f + ex2f(fmaf(xv[m].y, a2n, k02n)));
            if (wstart + g < 0) ol = 0.0f;
            sw[SK4(g)] = make_float4(xv[m].x, xv[m].y, ol, 0.0f);
        }
    }

    // ---- std partial reduce (warp level, fixed order -> deterministic) ----
    #pragma unroll
    for (int o = 16; o > 0; o >>= 1) {
        pa += __shfl_down_sync(0xffffffffu, pa, o);
        pb += __shfl_down_sync(0xffffffffu, pb, o);
    }
    if ((tid & 31) == 0) { rs[(tid >> 5) * 2] = pa; rs[(tid >> 5) * 2 + 1] = pb; }
    __syncthreads();                          // barrier #1: sw + rs visible

    // tid 0 finalizes sstd now — hidden under the other threads' warmup;
    // it is only read after barrier #2 (post-output), which tid 0 also passes.
    if (tid == 0) {
        float sa = (rs[0] + rs[2]) + (rs[4] + rs[6]);
        float sb = (rs[1] + rs[3]) + (rs[5] + rs[7]);
        const float n = (float)STD_N;
        float mean = sa / n;
        sstd = sqrtf((sb - sa * mean) / (n - 1.0f));
    }

    const int g0 = tid * CHT;          // chain window start (multiple of 4)
    float c = 0.0f;

    // ---- warmup: divide-free, affine smem addressing ----
    // 4-aligned 4-step ranges never cross an 8-boundary -> (g)>>3 constant
    // per range -> base pointer + immediate offsets.
    // step: m = min(u1, thr-c); olcc = min(ol*c, u2); c' = fma(-oo1*c, s, (c-olcc)+m)
    #pragma unroll
    for (int k0 = 0; k0 < WARM; k0 += 4) {
        const float4* p = &sw[SK4(g0 + k0)];
        #pragma unroll
        for (int k = 0; k < 4; ++k) {
            float4 v = p[k];
            float s    = rcpf(1.0f + ex2f(fmaf(c, a1n, k01n)));
            float t    = oo1 * c;
            float olcc = fminf(v.z * c, v.y);
            float m    = fminf(v.x, thr - c);
            c = fmaf(-t, s, (c - olcc) + m);
        }
    }

    // ---- output phase: 4 steps into smem transpose buffer ----
    const int sb0 = CHT * tid + (tid >> 3);   // SKO(4*tid), k-invariant base
    {
        const float4* p = &sw[SK4(g0 + WARM)];
        #pragma unroll
        for (int k = 0; k < CHT; ++k) {
            float4 v = p[k];
            float* q = &ob[sb0 + k];

            float s    = rcpf(1.0f + ex2f(fmaf(c, a1n, k01n)));
            float oo   = oo1 * s;
            float ooc  = oo * c;
            float olc  = (c > 0.0f) ? fminf(v.z, v.y * rcpf(c)) : v.z;
            float olcc = olc * c;
            float px   = fmaxf(v.x + c - thr, 0.0f);
            float ib   = (v.x > 0.0f) ? px * rcpf(v.x) : 0.0f;
            float f    = (1.0f - oo) - olc;

            q[0 * SOUT] = ooc + px;   // h_n
            q[1 * SOUT] = c;          // c_n (pre-update)
            q[2 * SOUT] = v.z * c;    // l_n
            q[3 * SOUT] = olcc;       // lc_n
            q[4 * SOUT] = px;         // bp_n
            q[5 * SOUT] = ib;         // g_ib
            q[6 * SOUT] = oo;         // g_oo
            q[7 * SOUT] = v.z;        // g_ol
            q[8 * SOUT] = olc;        // g_olc
            q[9 * SOUT] = f;          // g_f

            c = ((c - ooc) - olcc) + (v.x - px);
        }
    }
    __syncthreads();                          // barrier #2: ob + sstd visible
    const float stdv = sstd;

    // ---- coalesced flush (also produces h_nout and obs_std streams) ----
    #pragma unroll
    for (int st = 0; st < 10; ++st) {
        #pragma unroll
        for (int m = 0; m < OUTB / TB; ++m) {
            int t = tid + TB * m;
            out[(size_t)st * B + base + t] = ob[st * SOUT + t + (t >> 5)];
        }
    }
    float2* o2 = reinterpret_cast<float2*>(out + 10 * (size_t)B);
    #pragma unroll
    for (int m = 0; m < OUTB / TB; ++m) {
        int t = tid + TB * m;
        o2[base + t] = make_float2(ob[t + (t >> 5)], stdv);   // h_nout = [h, std]
        out[12 * (size_t)B + base + t] = stdv;                // obs_std
    }
}

// ---------------- launch ----------------
extern "C" void kernel_launch(void* const* d_in, const int* in_sizes, int n_in,
                              void* d_out, int out_size)
{
    const float* x = (const float*)d_in[0];
    const float* y = (const float*)d_in[1];
    float* out = (float*)d_out;
    const int B = in_sizes[0] / 2;   // 262144

    k_std1<<<SB, 256>>>(y,
                        (const float*)d_in[2], (const float*)d_in[3],
                        (const float*)d_in[4], (const float*)d_in[5],
                        (const float*)d_in[6], (const float*)d_in[7],
                        (const float*)d_in[8], (const float*)d_in[9],
                        (const float*)d_in[10], (const float*)d_in[11]);

    const int blocks = B / OUTB;     // 512 blocks x 128 threads
    k_scan<<<blocks, TB>>>(x, out, B);
}